// round 10
// baseline (speedup 1.0000x reference)
#include <cuda_runtime.h>
#include <cuda_bf16.h>
#include <cuda_fp8.h>
#include <math.h>
#include <stdint.h>

// ---------------- problem constants ----------------
#define NROWS 4096      // 2*B
#define D     512
#define HALF  2048      // B
#define PSLOTS 128      // 32 column tiles * 4 warp_n strips
#define FBLOCKS 128     // finalize blocks
#define SCALE 16.0f     // fp8 pre-scale; S accumulator carries 256x

// ---------------- device scratch (no allocs) ----------------
__device__ uint8_t g_z8[NROWS * D];            // normalized rows, e4m3 x16 (2 MB)
__device__ float g_partial[NROWS * PSLOTS];    // exp row-sum partials (2 MB)
__device__ float g_pos[NROWS];                 // fp32-accurate positive dots
__device__ float g_diag[NROWS];                // fp8-consistent diagonal (true scale)
__device__ float g_blk[FBLOCKS];
__device__ int   g_cnt;                         // zero-init, self-resetting

// SMEM: two buffers, each A[128][144B] + B[128][144B]
#define ROWB 144
#define TILE_BYTES (128 * ROWB)          // 18432
#define BUF_BYTES  (2 * TILE_BYTES)      // 36864
#define SMEM_TOT   (2 * BUF_BYTES)       // 73728

__device__ __forceinline__ uint32_t smem_u32(const void* p) {
    uint32_t a;
    asm("{ .reg .u64 t; cvta.to.shared.u64 t, %1; cvt.u32.u64 %0, t; }" : "=r"(a) : "l"(p));
    return a;
}

// exp(2S) from the 256x-scaled accumulator a=256*S: T4 with scale folded, squared.
__device__ __forceinline__ float expacc(float a) {
    float t = fmaf(a, 9.701278e-12f, 9.934107e-9f);   // 1/(24*256^4), 1/(6*256^3)
    t = fmaf(t, a, 7.62939453125e-6f);                // 1/(2*256^2)
    t = fmaf(t, a, 3.90625e-3f);                      // 1/256
    t = fmaf(t, a, 1.0f);
    return t * t;
}
// exp(2d) for true-scale diag (same functional form -> exact cancellation)
__device__ __forceinline__ float expdiag(float d) {
    float t = fmaf(d, 4.1666667e-2f, 1.6666667e-1f);
    t = fmaf(t, d, 0.5f);
    t = fmaf(t, d, 1.0f);
    t = fmaf(t, d, 1.0f);
    return t * t;
}
// accurate exp(2s) for the pos term: (T5(s/2))^4
__device__ __forceinline__ float exp2S(float s) {
    float y = 0.5f * s;
    float p = fmaf(y, 8.3333333e-3f, 4.1666667e-2f);
    p = fmaf(p, y, 1.6666667e-1f);
    p = fmaf(p, y, 0.5f);
    p = fmaf(p, y, 1.0f);
    p = fmaf(p, y, 1.0f);
    p = p * p;
    return p * p;
}

__device__ __forceinline__ float warp_xor_sum(float v) {
    #pragma unroll
    for (int o = 16; o > 0; o >>= 1)
        v += __shfl_xor_sync(0xffffffffu, v, o);
    return v;
}

__device__ __forceinline__ uint16_t f2_to_e4m3x2(float2 f) {
    return (uint16_t)__nv_cvt_float2_to_fp8x2(f, __NV_SATFINITE, __NV_E4M3);
}
__device__ __forceinline__ float2 e4m3x2_to_f2(uint16_t u) {
    __half2_raw hr = __nv_cvt_fp8x2_to_halfraw2((__nv_fp8x2_storage_t)u, __NV_E4M3);
    __half2 h = *reinterpret_cast<__half2*>(&hr);
    return __half22float2(h);
}

// ============================================================
// Kernel 1: normalize + pos/diag, warp-per-pair (R8 form).
// ============================================================
__global__ void __launch_bounds__(256) normpos_k(const float* __restrict__ zi,
                                                 const float* __restrict__ zj)
{
    const int warp = threadIdx.x >> 5;
    const int lane = threadIdx.x & 31;
    const int r = blockIdx.x * 8 + warp;

    const float4* ra4 = reinterpret_cast<const float4*>(zi + (size_t)r * D);
    const float4* rb4 = reinterpret_cast<const float4*>(zj + (size_t)r * D);

    float4 a[4], b[4];
    #pragma unroll
    for (int q = 0; q < 4; q++) {
        a[q] = ra4[lane + 32 * q];
        b[q] = rb4[lane + 32 * q];
    }

    float sa = 0.0f, sb = 0.0f;
    #pragma unroll
    for (int q = 0; q < 4; q++) {
        sa += a[q].x * a[q].x + a[q].y * a[q].y + a[q].z * a[q].z + a[q].w * a[q].w;
        sb += b[q].x * b[q].x + b[q].y * b[q].y + b[q].z * b[q].z + b[q].w * b[q].w;
    }
    sa = warp_xor_sum(sa);
    sb = warp_xor_sum(sb);
    const float invA = 1.0f / fmaxf(sqrtf(sa), 1e-8f);
    const float invB = 1.0f / fmaxf(sqrtf(sb), 1e-8f);
    const float qA = invA * SCALE;
    const float qB = invB * SCALE;

    uint32_t* da = reinterpret_cast<uint32_t*>(g_z8 + (size_t)r * D);
    uint32_t* db = reinterpret_cast<uint32_t*>(g_z8 + (size_t)(r + HALF) * D);

    float pp = 0.0f, dA = 0.0f, dB = 0.0f;
    #pragma unroll
    for (int q = 0; q < 4; q++) {
        pp += (a[q].x * invA) * (b[q].x * invB) + (a[q].y * invA) * (b[q].y * invB)
            + (a[q].z * invA) * (b[q].z * invB) + (a[q].w * invA) * (b[q].w * invB);

        uint16_t a01 = f2_to_e4m3x2(make_float2(a[q].x * qA, a[q].y * qA));
        uint16_t a23 = f2_to_e4m3x2(make_float2(a[q].z * qA, a[q].w * qA));
        uint16_t b01 = f2_to_e4m3x2(make_float2(b[q].x * qB, b[q].y * qB));
        uint16_t b23 = f2_to_e4m3x2(make_float2(b[q].z * qB, b[q].w * qB));

        da[lane + 32 * q] = (uint32_t)a01 | ((uint32_t)a23 << 16);
        db[lane + 32 * q] = (uint32_t)b01 | ((uint32_t)b23 << 16);

        float2 fa0 = e4m3x2_to_f2(a01), fa1 = e4m3x2_to_f2(a23);
        float2 fb0 = e4m3x2_to_f2(b01), fb1 = e4m3x2_to_f2(b23);
        dA += fa0.x * fa0.x + fa0.y * fa0.y + fa1.x * fa1.x + fa1.y * fa1.y;
        dB += fb0.x * fb0.x + fb0.y * fb0.y + fb1.x * fb1.x + fb1.y * fb1.y;
    }
    pp = warp_xor_sum(pp);
    dA = warp_xor_sum(dA);
    dB = warp_xor_sum(dB);
    if (lane == 0) {
        g_pos[r] = pp; g_pos[r + HALF] = pp;
        g_diag[r] = dA * (1.0f / 256.0f);
        g_diag[r + HALF] = dB * (1.0f / 256.0f);
    }
}

// ============================================================
// Kernel 2: symmetric e4m3 GEMM, 512 threads = 4x4 warps of
// 32x32 tiles (32 regs acc -> 2 CTAs/SM = 32 warps/SM).
// 2-D grid, lower triangle exits. Row-sums always; col-sums
// (per warp_m quarter) for off-diagonal tiles.
// ============================================================
__global__ void __launch_bounds__(512, 2) gemm_expsum_k()
{
    const int brow = blockIdx.y;
    const int bcol = blockIdx.x;
    if (brow > bcol) return;

    extern __shared__ __align__(128) char smem[];
    const uint32_t sbase = smem_u32(smem);

    const int tid  = threadIdx.x;
    const int lane = tid & 31;
    const int wid  = tid >> 5;
    const int warp_m = wid >> 2;   // 0..3
    const int warp_n = wid & 3;    // 0..3

    const uint8_t* Ab = g_z8 + (size_t)(brow * 128) * D;
    const uint8_t* Bb = g_z8 + (size_t)(bcol * 128) * D;

    auto load_chunk = [&](int c) {
        const uint32_t sa = sbase + (uint32_t)(c & 1) * BUF_BYTES;
        const uint32_t sb = sa + TILE_BYTES;
        const int k0 = c * 128;
        #pragma unroll
        for (int i = 0; i < 2; i++) {
            int idx = tid + i * 512;
            int row = idx >> 3, cc = idx & 7;
            uint32_t so = (uint32_t)(row * ROWB + cc * 16);
            const uint8_t* ga = Ab + (size_t)row * D + k0 + cc * 16;
            const uint8_t* gb = Bb + (size_t)row * D + k0 + cc * 16;
            asm volatile("cp.async.cg.shared.global [%0], [%1], 16;" :: "r"(sa + so), "l"(ga));
            asm volatile("cp.async.cg.shared.global [%0], [%1], 16;" :: "r"(sb + so), "l"(gb));
        }
        asm volatile("cp.async.commit_group;");
    };

    float acc[2][4][4];
    #pragma unroll
    for (int mf = 0; mf < 2; mf++)
        #pragma unroll
        for (int nf = 0; nf < 4; nf++)
            #pragma unroll
            for (int e = 0; e < 4; e++) acc[mf][nf][e] = 0.0f;

    load_chunk(0);

    #pragma unroll 1
    for (int c = 0; c < 4; c++) {
        if (c < 3) {
            load_chunk(c + 1);
            asm volatile("cp.async.wait_group 1;");
        } else {
            asm volatile("cp.async.wait_group 0;");
        }
        __syncthreads();

        const uint32_t sa = sbase + (uint32_t)(c & 1) * BUF_BYTES;
        const uint32_t sb = sa + TILE_BYTES;

        #pragma unroll
        for (int ks = 0; ks < 4; ks++) {
            uint32_t a[2][4];
            #pragma unroll
            for (int mf = 0; mf < 2; mf++) {
                int row = warp_m * 32 + mf * 16 + (lane & 15);
                int col = ks * 32 + (lane >> 4) * 16;
                uint32_t addr = sa + (uint32_t)(row * ROWB + col);
                asm volatile("ldmatrix.sync.aligned.m8n8.x4.shared.b16 {%0,%1,%2,%3},[%4];"
                    : "=r"(a[mf][0]), "=r"(a[mf][1]), "=r"(a[mf][2]), "=r"(a[mf][3])
                    : "r"(addr));
            }
            #pragma unroll
            for (int nf16 = 0; nf16 < 2; nf16++) {
                int sub = lane >> 3, wi = lane & 7;
                int nrow = warp_n * 32 + nf16 * 16 + ((sub & 2) ? 8 : 0) + wi;
                int kcol = ks * 32 + ((sub & 1) ? 16 : 0);
                uint32_t addr = sb + (uint32_t)(nrow * ROWB + kcol);
                uint32_t b0, b1, b2, b3;
                asm volatile("ldmatrix.sync.aligned.m8n8.x4.shared.b16 {%0,%1,%2,%3},[%4];"
                    : "=r"(b0), "=r"(b1), "=r"(b2), "=r"(b3) : "r"(addr));
                #pragma unroll
                for (int mf = 0; mf < 2; mf++) {
                    float* c0 = acc[mf][2 * nf16];
                    float* c1 = acc[mf][2 * nf16 + 1];
                    asm volatile(
                        "mma.sync.aligned.m16n8k32.row.col.f32.e4m3.e4m3.f32 "
                        "{%0,%1,%2,%3},{%4,%5,%6,%7},{%8,%9},{%0,%1,%2,%3};"
                        : "+f"(c0[0]), "+f"(c0[1]), "+f"(c0[2]), "+f"(c0[3])
                        : "r"(a[mf][0]), "r"(a[mf][1]), "r"(a[mf][2]), "r"(a[mf][3]),
                          "r"(b0), "r"(b1));
                    asm volatile(
                        "mma.sync.aligned.m16n8k32.row.col.f32.e4m3.e4m3.f32 "
                        "{%0,%1,%2,%3},{%4,%5,%6,%7},{%8,%9},{%0,%1,%2,%3};"
                        : "+f"(c1[0]), "+f"(c1[1]), "+f"(c1[2]), "+f"(c1[3])
                        : "r"(a[mf][0]), "r"(a[mf][1]), "r"(a[mf][2]), "r"(a[mf][3]),
                          "r"(b2), "r"(b3));
                }
            }
        }
        __syncthreads();
    }

    // --- epilogue: exp in place ---
    #pragma unroll
    for (int mf = 0; mf < 2; mf++)
        #pragma unroll
        for (int nf = 0; nf < 4; nf++)
            #pragma unroll
            for (int e = 0; e < 4; e++)
                acc[mf][nf][e] = expacc(acc[mf][nf][e]);

    // row-sums: rows of brow tile, 32-col strip per warp_n
    #pragma unroll
    for (int mf = 0; mf < 2; mf++) {
        float rlo = 0.0f, rhi = 0.0f;
        #pragma unroll
        for (int nf = 0; nf < 4; nf++) {
            rlo += acc[mf][nf][0] + acc[mf][nf][1];
            rhi += acc[mf][nf][2] + acc[mf][nf][3];
        }
        rlo += __shfl_xor_sync(0xffffffffu, rlo, 1);
        rlo += __shfl_xor_sync(0xffffffffu, rlo, 2);
        rhi += __shfl_xor_sync(0xffffffffu, rhi, 1);
        rhi += __shfl_xor_sync(0xffffffffu, rhi, 2);
        if ((lane & 3) == 0) {
            int r0 = brow * 128 + warp_m * 32 + mf * 16 + (lane >> 2);
            int slot = bcol * 4 + warp_n;
            g_partial[(size_t)r0 * PSLOTS + slot] = rlo;
            g_partial[(size_t)(r0 + 8) * PSLOTS + slot] = rhi;
        }
    }

    if (brow != bcol) {
        // col-sums over this warp's 32 rows; per-warp_m quarters go to
        // separate slots (no cross-warp reduce needed).
        float cs[8];
        #pragma unroll
        for (int nf = 0; nf < 4; nf++)
            #pragma unroll
            for (int e = 0; e < 2; e++)
                cs[nf * 2 + e] = acc[0][nf][e] + acc[0][nf][e + 2]
                               + acc[1][nf][e] + acc[1][nf][e + 2];
        #pragma unroll
        for (int i = 0; i < 8; i++) {
            cs[i] += __shfl_xor_sync(0xffffffffu, cs[i], 4);
            cs[i] += __shfl_xor_sync(0xffffffffu, cs[i], 8);
            cs[i] += __shfl_xor_sync(0xffffffffu, cs[i], 16);
        }
        float* scol = reinterpret_cast<float*>(smem);  // [4][128]
        __syncthreads();
        if (lane < 4) {
            #pragma unroll
            for (int nf = 0; nf < 4; nf++)
                #pragma unroll
                for (int e = 0; e < 2; e++) {
                    int col = warp_n * 32 + nf * 8 + lane * 2 + e;
                    scol[warp_m * 128 + col] = cs[nf * 2 + e];
                }
        }
        __syncthreads();
        {
            int q = tid >> 7;          // warp_m quarter 0..3
            int cc = tid & 127;        // column
            g_partial[(size_t)(bcol * 128 + cc) * PSLOTS + brow * 4 + q] = scol[q * 128 + cc];
        }
    }
}

// ============================================================
// Kernel 3: single fused finalize. Warp per row (float4 covers
// 128 slots); last block reduces deterministically, resets cnt.
// ============================================================
__global__ void __launch_bounds__(1024) finalize_k(float* __restrict__ out)
{
    const int warp = threadIdx.x >> 5;
    const int lane = threadIdx.x & 31;
    const int row  = blockIdx.x * 32 + warp;

    float4 v4 = reinterpret_cast<const float4*>(g_partial + (size_t)row * PSLOTS)[lane];
    float s = (v4.x + v4.y) + (v4.z + v4.w);
    #pragma unroll
    for (int o = 16; o > 0; o >>= 1)
        s += __shfl_down_sync(0xffffffffu, s, o);

    __shared__ float red[32];
    if (lane == 0) {
        float pos = g_pos[row], diag = g_diag[row];
        float tot = s - expdiag(diag) + exp2S(pos);
        red[warp] = logf(tot) - 2.0f * pos;
    }
    __syncthreads();

    __shared__ bool amlast;
    if (threadIdx.x < 32) {
        float v = red[threadIdx.x];
        #pragma unroll
        for (int o = 16; o > 0; o >>= 1)
            v += __shfl_down_sync(0xffffffffu, v, o);
        if (threadIdx.x == 0) {
            g_blk[blockIdx.x] = v;
            __threadfence();
            int old = atomicAdd(&g_cnt, 1);
            amlast = (old == FBLOCKS - 1);
        }
    }
    __syncthreads();

    if (amlast && threadIdx.x < 32) {
        __threadfence();
        float v = 0.0f;
        #pragma unroll
        for (int q = 0; q < FBLOCKS / 32; q++)
            v += g_blk[q * 32 + lane];
        #pragma unroll
        for (int o = 16; o > 0; o >>= 1)
            v += __shfl_down_sync(0xffffffffu, v, o);
        if (lane == 0) {
            out[0] = v / (float)NROWS;
            g_cnt = 0;
        }
    }
}

// ============================================================
extern "C" void kernel_launch(void* const* d_in, const int* in_sizes, int n_in,
                              void* d_out, int out_size)
{
    const float* zi = (const float*)d_in[0];
    const float* zj = (const float*)d_in[1];
    float* out = (float*)d_out;

    cudaFuncSetAttribute(gemm_expsum_k,
                         cudaFuncAttributeMaxDynamicSharedMemorySize, SMEM_TOT);

    normpos_k<<<HALF / 8, 256>>>(zi, zj);
    dim3 grid(NROWS / 128, NROWS / 128);   // (32, 32), lower triangle exits
    gemm_expsum_k<<<grid, 512, SMEM_TOT>>>();
    finalize_k<<<FBLOCKS, 1024>>>(out);
}

// round 11
// speedup vs baseline: 1.0433x; 1.0433x over previous
#include <cuda_runtime.h>
#include <cuda_bf16.h>
#include <cuda_fp8.h>
#include <math.h>
#include <stdint.h>

// ---------------- problem constants ----------------
#define NROWS 4096      // 2*B
#define D     512
#define HALF  2048      // B
#define PSLOTS 128      // 64 col tiles * 2 strips (row-sums) / 32*4 (col-sums)
#define FBLOCKS 128     // finalize blocks
#define SCALE 16.0f     // fp8 pre-scale; S accumulator carries 256x

// ---------------- device scratch (no allocs) ----------------
__device__ uint8_t g_z8[NROWS * D];            // normalized rows, e4m3 x16 (2 MB)
__device__ float g_partial[NROWS * PSLOTS];    // exp row-sum partials (2 MB)
__device__ float g_pos[NROWS];
__device__ float g_diag[NROWS];
__device__ float g_blk[FBLOCKS];
__device__ int   g_cnt;                         // zero-init, self-resetting

// SMEM: two buffers, each A[128][144B] + B[64][144B]
#define ROWB 144
#define A_BYTES (128 * ROWB)             // 18432
#define B_BYTES (64 * ROWB)              // 9216
#define BUF_BYTES (A_BYTES + B_BYTES)    // 27648
#define SMEM_TOT  (2 * BUF_BYTES)        // 55296

__device__ __forceinline__ uint32_t smem_u32(const void* p) {
    uint32_t a;
    asm("{ .reg .u64 t; cvta.to.shared.u64 t, %1; cvt.u32.u64 %0, t; }" : "=r"(a) : "l"(p));
    return a;
}

// exp(2S) from the 256x-scaled accumulator a=256*S: T4 with scale folded, squared.
__device__ __forceinline__ float expacc(float a) {
    float t = fmaf(a, 9.701278e-12f, 9.934107e-9f);
    t = fmaf(t, a, 7.62939453125e-6f);
    t = fmaf(t, a, 3.90625e-3f);
    t = fmaf(t, a, 1.0f);
    return t * t;
}
__device__ __forceinline__ float expdiag(float d) {
    float t = fmaf(d, 4.1666667e-2f, 1.6666667e-1f);
    t = fmaf(t, d, 0.5f);
    t = fmaf(t, d, 1.0f);
    t = fmaf(t, d, 1.0f);
    return t * t;
}
__device__ __forceinline__ float exp2S(float s) {
    float y = 0.5f * s;
    float p = fmaf(y, 8.3333333e-3f, 4.1666667e-2f);
    p = fmaf(p, y, 1.6666667e-1f);
    p = fmaf(p, y, 0.5f);
    p = fmaf(p, y, 1.0f);
    p = fmaf(p, y, 1.0f);
    p = p * p;
    return p * p;
}

__device__ __forceinline__ float warp_xor_sum(float v) {
    #pragma unroll
    for (int o = 16; o > 0; o >>= 1)
        v += __shfl_xor_sync(0xffffffffu, v, o);
    return v;
}

__device__ __forceinline__ uint16_t f2_to_e4m3x2(float2 f) {
    return (uint16_t)__nv_cvt_float2_to_fp8x2(f, __NV_SATFINITE, __NV_E4M3);
}
__device__ __forceinline__ float2 e4m3x2_to_f2(uint16_t u) {
    __half2_raw hr = __nv_cvt_fp8x2_to_halfraw2((__nv_fp8x2_storage_t)u, __NV_E4M3);
    __half2 h = *reinterpret_cast<__half2*>(&hr);
    return __half22float2(h);
}

// ============================================================
// Kernel 1: normalize + pos/diag, warp-per-pair (R8 form).
// ============================================================
__global__ void __launch_bounds__(256) normpos_k(const float* __restrict__ zi,
                                                 const float* __restrict__ zj)
{
    const int warp = threadIdx.x >> 5;
    const int lane = threadIdx.x & 31;
    const int r = blockIdx.x * 8 + warp;

    const float4* ra4 = reinterpret_cast<const float4*>(zi + (size_t)r * D);
    const float4* rb4 = reinterpret_cast<const float4*>(zj + (size_t)r * D);

    float4 a[4], b[4];
    #pragma unroll
    for (int q = 0; q < 4; q++) {
        a[q] = ra4[lane + 32 * q];
        b[q] = rb4[lane + 32 * q];
    }

    float sa = 0.0f, sb = 0.0f;
    #pragma unroll
    for (int q = 0; q < 4; q++) {
        sa += a[q].x * a[q].x + a[q].y * a[q].y + a[q].z * a[q].z + a[q].w * a[q].w;
        sb += b[q].x * b[q].x + b[q].y * b[q].y + b[q].z * b[q].z + b[q].w * b[q].w;
    }
    sa = warp_xor_sum(sa);
    sb = warp_xor_sum(sb);
    const float invA = 1.0f / fmaxf(sqrtf(sa), 1e-8f);
    const float invB = 1.0f / fmaxf(sqrtf(sb), 1e-8f);
    const float qA = invA * SCALE;
    const float qB = invB * SCALE;

    uint32_t* da = reinterpret_cast<uint32_t*>(g_z8 + (size_t)r * D);
    uint32_t* db = reinterpret_cast<uint32_t*>(g_z8 + (size_t)(r + HALF) * D);

    float pp = 0.0f, dA = 0.0f, dB = 0.0f;
    #pragma unroll
    for (int q = 0; q < 4; q++) {
        pp += (a[q].x * invA) * (b[q].x * invB) + (a[q].y * invA) * (b[q].y * invB)
            + (a[q].z * invA) * (b[q].z * invB) + (a[q].w * invA) * (b[q].w * invB);

        uint16_t a01 = f2_to_e4m3x2(make_float2(a[q].x * qA, a[q].y * qA));
        uint16_t a23 = f2_to_e4m3x2(make_float2(a[q].z * qA, a[q].w * qA));
        uint16_t b01 = f2_to_e4m3x2(make_float2(b[q].x * qB, b[q].y * qB));
        uint16_t b23 = f2_to_e4m3x2(make_float2(b[q].z * qB, b[q].w * qB));

        da[lane + 32 * q] = (uint32_t)a01 | ((uint32_t)a23 << 16);
        db[lane + 32 * q] = (uint32_t)b01 | ((uint32_t)b23 << 16);

        float2 fa0 = e4m3x2_to_f2(a01), fa1 = e4m3x2_to_f2(a23);
        float2 fb0 = e4m3x2_to_f2(b01), fb1 = e4m3x2_to_f2(b23);
        dA += fa0.x * fa0.x + fa0.y * fa0.y + fa1.x * fa1.x + fa1.y * fa1.y;
        dB += fb0.x * fb0.x + fb0.y * fb0.y + fb1.x * fb1.x + fb1.y * fb1.y;
    }
    pp = warp_xor_sum(pp);
    dA = warp_xor_sum(dA);
    dB = warp_xor_sum(dB);
    if (lane == 0) {
        g_pos[r] = pp; g_pos[r + HALF] = pp;
        g_diag[r] = dA * (1.0f / 256.0f);
        g_diag[r + HALF] = dB * (1.0f / 256.0f);
    }
}

// ============================================================
// Kernel 2: symmetric e4m3 GEMM, 128x64 tiles, 256 threads =
// 4(m) x 2(n) warps of 32x32 (acc=32 regs -> 3 CTAs/SM).
// Grid (64, 32): keep tiles with bcol >= 2*brow (1056 active).
// Diagonal pairs (bcol>>1 == brow): row-sums only.
// ============================================================
__global__ void __launch_bounds__(256, 3) gemm_expsum_k()
{
    const int brow = blockIdx.y;        // 128-row block, 0..31
    const int bcol = blockIdx.x;        // 64-col block, 0..63
    if (bcol < 2 * brow) return;        // symmetry: skip lower triangle
    const bool offdiag = ((bcol >> 1) != brow);

    extern __shared__ __align__(128) char smem[];
    const uint32_t sbase = smem_u32(smem);

    const int tid  = threadIdx.x;
    const int lane = tid & 31;
    const int wid  = tid >> 5;
    const int warp_m = wid >> 1;   // 0..3
    const int warp_n = wid & 1;    // 0..1

    const uint8_t* Ab = g_z8 + (size_t)(brow * 128) * D;
    const uint8_t* Bb = g_z8 + (size_t)(bcol * 64) * D;

    auto load_chunk = [&](int c) {
        const uint32_t sa = sbase + (uint32_t)(c & 1) * BUF_BYTES;
        const uint32_t sb = sa + A_BYTES;
        const int k0 = c * 128;
        #pragma unroll
        for (int i = 0; i < 4; i++) {       // A: 1024 x 16B
            int idx = tid + i * 256;
            int row = idx >> 3, cc = idx & 7;
            uint32_t so = (uint32_t)(row * ROWB + cc * 16);
            const uint8_t* ga = Ab + (size_t)row * D + k0 + cc * 16;
            asm volatile("cp.async.cg.shared.global [%0], [%1], 16;" :: "r"(sa + so), "l"(ga));
        }
        #pragma unroll
        for (int i = 0; i < 2; i++) {       // B: 512 x 16B
            int idx = tid + i * 256;
            int row = idx >> 3, cc = idx & 7;
            uint32_t so = (uint32_t)(row * ROWB + cc * 16);
            const uint8_t* gb = Bb + (size_t)row * D + k0 + cc * 16;
            asm volatile("cp.async.cg.shared.global [%0], [%1], 16;" :: "r"(sb + so), "l"(gb));
        }
        asm volatile("cp.async.commit_group;");
    };

    float acc[2][4][4];
    #pragma unroll
    for (int mf = 0; mf < 2; mf++)
        #pragma unroll
        for (int nf = 0; nf < 4; nf++)
            #pragma unroll
            for (int e = 0; e < 4; e++) acc[mf][nf][e] = 0.0f;

    load_chunk(0);

    #pragma unroll 1
    for (int c = 0; c < 4; c++) {
        if (c < 3) {
            load_chunk(c + 1);
            asm volatile("cp.async.wait_group 1;");
        } else {
            asm volatile("cp.async.wait_group 0;");
        }
        __syncthreads();

        const uint32_t sa = sbase + (uint32_t)(c & 1) * BUF_BYTES;
        const uint32_t sb = sa + A_BYTES;

        #pragma unroll
        for (int ks = 0; ks < 4; ks++) {
            uint32_t a[2][4];
            #pragma unroll
            for (int mf = 0; mf < 2; mf++) {
                int row = warp_m * 32 + mf * 16 + (lane & 15);
                int col = ks * 32 + (lane >> 4) * 16;
                uint32_t addr = sa + (uint32_t)(row * ROWB + col);
                asm volatile("ldmatrix.sync.aligned.m8n8.x4.shared.b16 {%0,%1,%2,%3},[%4];"
                    : "=r"(a[mf][0]), "=r"(a[mf][1]), "=r"(a[mf][2]), "=r"(a[mf][3])
                    : "r"(addr));
            }
            #pragma unroll
            for (int nf16 = 0; nf16 < 2; nf16++) {
                int sub = lane >> 3, wi = lane & 7;
                int nrow = warp_n * 32 + nf16 * 16 + ((sub & 2) ? 8 : 0) + wi;
                int kcol = ks * 32 + ((sub & 1) ? 16 : 0);
                uint32_t addr = sb + (uint32_t)(nrow * ROWB + kcol);
                uint32_t b0, b1, b2, b3;
                asm volatile("ldmatrix.sync.aligned.m8n8.x4.shared.b16 {%0,%1,%2,%3},[%4];"
                    : "=r"(b0), "=r"(b1), "=r"(b2), "=r"(b3) : "r"(addr));
                #pragma unroll
                for (int mf = 0; mf < 2; mf++) {
                    float* c0 = acc[mf][2 * nf16];
                    float* c1 = acc[mf][2 * nf16 + 1];
                    asm volatile(
                        "mma.sync.aligned.m16n8k32.row.col.f32.e4m3.e4m3.f32 "
                        "{%0,%1,%2,%3},{%4,%5,%6,%7},{%8,%9},{%0,%1,%2,%3};"
                        : "+f"(c0[0]), "+f"(c0[1]), "+f"(c0[2]), "+f"(c0[3])
                        : "r"(a[mf][0]), "r"(a[mf][1]), "r"(a[mf][2]), "r"(a[mf][3]),
                          "r"(b0), "r"(b1));
                    asm volatile(
                        "mma.sync.aligned.m16n8k32.row.col.f32.e4m3.e4m3.f32 "
                        "{%0,%1,%2,%3},{%4,%5,%6,%7},{%8,%9},{%0,%1,%2,%3};"
                        : "+f"(c1[0]), "+f"(c1[1]), "+f"(c1[2]), "+f"(c1[3])
                        : "r"(a[mf][0]), "r"(a[mf][1]), "r"(a[mf][2]), "r"(a[mf][3]),
                          "r"(b2), "r"(b3));
                }
            }
        }
        __syncthreads();
    }

    // --- epilogue: exp in place ---
    #pragma unroll
    for (int mf = 0; mf < 2; mf++)
        #pragma unroll
        for (int nf = 0; nf < 4; nf++)
            #pragma unroll
            for (int e = 0; e < 4; e++)
                acc[mf][nf][e] = expacc(acc[mf][nf][e]);

    // row-sums: rows of brow tile; slot = 2*bcol + warp_n (range 4*brow..127)
    #pragma unroll
    for (int mf = 0; mf < 2; mf++) {
        float rlo = 0.0f, rhi = 0.0f;
        #pragma unroll
        for (int nf = 0; nf < 4; nf++) {
            rlo += acc[mf][nf][0] + acc[mf][nf][1];
            rhi += acc[mf][nf][2] + acc[mf][nf][3];
        }
        rlo += __shfl_xor_sync(0xffffffffu, rlo, 1);
        rlo += __shfl_xor_sync(0xffffffffu, rlo, 2);
        rhi += __shfl_xor_sync(0xffffffffu, rhi, 1);
        rhi += __shfl_xor_sync(0xffffffffu, rhi, 2);
        if ((lane & 3) == 0) {
            int r0 = brow * 128 + warp_m * 32 + mf * 16 + (lane >> 2);
            int slot = bcol * 2 + warp_n;
            g_partial[(size_t)r0 * PSLOTS + slot] = rlo;
            g_partial[(size_t)(r0 + 8) * PSLOTS + slot] = rhi;
        }
    }

    // col-sums (off-diagonal only): direct register stores, no smem.
    // transposed row = bcol*64 + local col; slot = 4*brow + warp_m (< 4*(bcol>>1))
    if (offdiag) {
        float cs[8];
        #pragma unroll
        for (int nf = 0; nf < 4; nf++)
            #pragma unroll
            for (int e = 0; e < 2; e++)
                cs[nf * 2 + e] = acc[0][nf][e] + acc[0][nf][e + 2]
                               + acc[1][nf][e] + acc[1][nf][e + 2];
        #pragma unroll
        for (int i = 0; i < 8; i++) {
            cs[i] += __shfl_xor_sync(0xffffffffu, cs[i], 4);
            cs[i] += __shfl_xor_sync(0xffffffffu, cs[i], 8);
            cs[i] += __shfl_xor_sync(0xffffffffu, cs[i], 16);
        }
        if (lane < 4) {
            const int slot = brow * 4 + warp_m;
            #pragma unroll
            for (int nf = 0; nf < 4; nf++)
                #pragma unroll
                for (int e = 0; e < 2; e++) {
                    int col = bcol * 64 + warp_n * 32 + nf * 8 + lane * 2 + e;
                    g_partial[(size_t)col * PSLOTS + slot] = cs[nf * 2 + e];
                }
        }
    }
}

// ============================================================
// Kernel 3: single fused finalize. Warp per row (float4 covers
// 128 slots); last block reduces deterministically, resets cnt.
// ============================================================
__global__ void __launch_bounds__(1024) finalize_k(float* __restrict__ out)
{
    const int warp = threadIdx.x >> 5;
    const int lane = threadIdx.x & 31;
    const int row  = blockIdx.x * 32 + warp;

    float4 v4 = reinterpret_cast<const float4*>(g_partial + (size_t)row * PSLOTS)[lane];
    float s = (v4.x + v4.y) + (v4.z + v4.w);
    #pragma unroll
    for (int o = 16; o > 0; o >>= 1)
        s += __shfl_down_sync(0xffffffffu, s, o);

    __shared__ float red[32];
    if (lane == 0) {
        float pos = g_pos[row], diag = g_diag[row];
        float tot = s - expdiag(diag) + exp2S(pos);
        red[warp] = logf(tot) - 2.0f * pos;
    }
    __syncthreads();

    __shared__ bool amlast;
    if (threadIdx.x < 32) {
        float v = red[threadIdx.x];
        #pragma unroll
        for (int o = 16; o > 0; o >>= 1)
            v += __shfl_down_sync(0xffffffffu, v, o);
        if (threadIdx.x == 0) {
            g_blk[blockIdx.x] = v;
            __threadfence();
            int old = atomicAdd(&g_cnt, 1);
            amlast = (old == FBLOCKS - 1);
        }
    }
    __syncthreads();

    if (amlast && threadIdx.x < 32) {
        __threadfence();
        float v = 0.0f;
        #pragma unroll
        for (int q = 0; q < FBLOCKS / 32; q++)
            v += g_blk[q * 32 + lane];
        #pragma unroll
        for (int o = 16; o > 0; o >>= 1)
            v += __shfl_down_sync(0xffffffffu, v, o);
        if (lane == 0) {
            out[0] = v / (float)NROWS;
            g_cnt = 0;
        }
    }
}

// ============================================================
extern "C" void kernel_launch(void* const* d_in, const int* in_sizes, int n_in,
                              void* d_out, int out_size)
{
    const float* zi = (const float*)d_in[0];
    const float* zj = (const float*)d_in[1];
    float* out = (float*)d_out;

    cudaFuncSetAttribute(gemm_expsum_k,
                         cudaFuncAttributeMaxDynamicSharedMemorySize, SMEM_TOT);

    normpos_k<<<HALF / 8, 256>>>(zi, zj);
    dim3 grid(64, 32);                 // keep bcol >= 2*brow (1056 active)
    gemm_expsum_k<<<grid, 256, SMEM_TOT>>>();
    finalize_k<<<FBLOCKS, 1024>>>(out);
}

// round 12
// speedup vs baseline: 1.1544x; 1.1066x over previous
#include <cuda_runtime.h>
#include <cuda_bf16.h>
#include <cuda_fp8.h>
#include <math.h>
#include <stdint.h>

// ---------------- problem constants ----------------
#define NROWS 4096      // 2*B
#define D     512
#define HALF  2048      // B
#define PSLOTS 64       // 32 column tiles * 2 halves
#define FBLOCKS 128     // finalize blocks
#define SCALE 16.0f     // fp8 pre-scale; S accumulator carries 256x

// ---------------- device scratch (no allocs) ----------------
__device__ uint8_t g_z8[NROWS * D];            // normalized rows, e4m3 x16 (2 MB)
__device__ float g_partial[NROWS * PSLOTS];    // exp row-sum partials (1 MB)
__device__ float g_pos[NROWS];
__device__ float g_diag[NROWS];
__device__ float g_blk[FBLOCKS];
__device__ int   g_cnt;                         // zero-init, self-resetting

// SMEM: two buffers, each A[128][144B] + B[128][144B]
#define ROWB 144
#define TILE_BYTES (128 * ROWB)          // 18432
#define BUF_BYTES  (2 * TILE_BYTES)      // 36864
#define SMEM_TOT   (2 * BUF_BYTES)       // 73728

__device__ __forceinline__ uint32_t smem_u32(const void* p) {
    uint32_t a;
    asm("{ .reg .u64 t; cvta.to.shared.u64 t, %1; cvt.u32.u64 %0, t; }" : "=r"(a) : "l"(p));
    return a;
}

// exp(2S) from the 256x-scaled accumulator a=256*S: T4 with scale folded, squared.
__device__ __forceinline__ float expacc(float a) {
    float t = fmaf(a, 9.701278e-12f, 9.934107e-9f);
    t = fmaf(t, a, 7.62939453125e-6f);
    t = fmaf(t, a, 3.90625e-3f);
    t = fmaf(t, a, 1.0f);
    return t * t;
}
__device__ __forceinline__ float expdiag(float d) {
    float t = fmaf(d, 4.1666667e-2f, 1.6666667e-1f);
    t = fmaf(t, d, 0.5f);
    t = fmaf(t, d, 1.0f);
    t = fmaf(t, d, 1.0f);
    return t * t;
}
__device__ __forceinline__ float exp2S(float s) {
    float y = 0.5f * s;
    float p = fmaf(y, 8.3333333e-3f, 4.1666667e-2f);
    p = fmaf(p, y, 1.6666667e-1f);
    p = fmaf(p, y, 0.5f);
    p = fmaf(p, y, 1.0f);
    p = fmaf(p, y, 1.0f);
    p = p * p;
    return p * p;
}

__device__ __forceinline__ float warp_xor_sum(float v) {
    #pragma unroll
    for (int o = 16; o > 0; o >>= 1)
        v += __shfl_xor_sync(0xffffffffu, v, o);
    return v;
}

__device__ __forceinline__ uint16_t f2_to_e4m3x2(float2 f) {
    return (uint16_t)__nv_cvt_float2_to_fp8x2(f, __NV_SATFINITE, __NV_E4M3);
}
__device__ __forceinline__ float2 e4m3x2_to_f2(uint16_t u) {
    __half2_raw hr = __nv_cvt_fp8x2_to_halfraw2((__nv_fp8x2_storage_t)u, __NV_E4M3);
    __half2 h = *reinterpret_cast<__half2*>(&hr);
    return __half22float2(h);
}

// process one pair given its preloaded data; writes z8/pos/diag
__device__ __forceinline__ void emit_pair(int r, int lane,
                                          const float4* a, const float4* b)
{
    float sa = 0.0f, sb = 0.0f;
    #pragma unroll
    for (int q = 0; q < 4; q++) {
        sa += a[q].x * a[q].x + a[q].y * a[q].y + a[q].z * a[q].z + a[q].w * a[q].w;
        sb += b[q].x * b[q].x + b[q].y * b[q].y + b[q].z * b[q].z + b[q].w * b[q].w;
    }
    sa = warp_xor_sum(sa);
    sb = warp_xor_sum(sb);
    const float invA = 1.0f / fmaxf(sqrtf(sa), 1e-8f);
    const float invB = 1.0f / fmaxf(sqrtf(sb), 1e-8f);
    const float qA = invA * SCALE;
    const float qB = invB * SCALE;

    uint32_t* da = reinterpret_cast<uint32_t*>(g_z8 + (size_t)r * D);
    uint32_t* db = reinterpret_cast<uint32_t*>(g_z8 + (size_t)(r + HALF) * D);

    float pp = 0.0f, dA = 0.0f, dB = 0.0f;
    #pragma unroll
    for (int q = 0; q < 4; q++) {
        pp += (a[q].x * invA) * (b[q].x * invB) + (a[q].y * invA) * (b[q].y * invB)
            + (a[q].z * invA) * (b[q].z * invB) + (a[q].w * invA) * (b[q].w * invB);

        uint16_t a01 = f2_to_e4m3x2(make_float2(a[q].x * qA, a[q].y * qA));
        uint16_t a23 = f2_to_e4m3x2(make_float2(a[q].z * qA, a[q].w * qA));
        uint16_t b01 = f2_to_e4m3x2(make_float2(b[q].x * qB, b[q].y * qB));
        uint16_t b23 = f2_to_e4m3x2(make_float2(b[q].z * qB, b[q].w * qB));

        da[lane + 32 * q] = (uint32_t)a01 | ((uint32_t)a23 << 16);
        db[lane + 32 * q] = (uint32_t)b01 | ((uint32_t)b23 << 16);

        float2 fa0 = e4m3x2_to_f2(a01), fa1 = e4m3x2_to_f2(a23);
        float2 fb0 = e4m3x2_to_f2(b01), fb1 = e4m3x2_to_f2(b23);
        dA += fa0.x * fa0.x + fa0.y * fa0.y + fa1.x * fa1.x + fa1.y * fa1.y;
        dB += fb0.x * fb0.x + fb0.y * fb0.y + fb1.x * fb1.x + fb1.y * fb1.y;
    }
    pp = warp_xor_sum(pp);
    dA = warp_xor_sum(dA);
    dB = warp_xor_sum(dB);
    if (lane == 0) {
        g_pos[r] = pp; g_pos[r + HALF] = pp;
        g_diag[r] = dA * (1.0f / 256.0f);
        g_diag[r + HALF] = dB * (1.0f / 256.0f);
    }
}

// ============================================================
// Kernel 1: normalize + pos/diag. TWO pairs per warp; all 16
// float4 loads issued before any reduction (2x MLP).
// 256 blocks x 128 threads = 1024 warps.
// ============================================================
__global__ void __launch_bounds__(128) normpos_k(const float* __restrict__ zi,
                                                 const float* __restrict__ zj)
{
    const int warp = threadIdx.x >> 5;
    const int lane = threadIdx.x & 31;
    const int w = blockIdx.x * 4 + warp;      // 0..1023
    const int r0 = w, r1 = w + 1024;

    const float4* ra0 = reinterpret_cast<const float4*>(zi + (size_t)r0 * D);
    const float4* rb0 = reinterpret_cast<const float4*>(zj + (size_t)r0 * D);
    const float4* ra1 = reinterpret_cast<const float4*>(zi + (size_t)r1 * D);
    const float4* rb1 = reinterpret_cast<const float4*>(zj + (size_t)r1 * D);

    // batch ALL loads first: 16 independent LDG.128 in flight
    float4 a0[4], b0[4], a1[4], b1[4];
    #pragma unroll
    for (int q = 0; q < 4; q++) a0[q] = ra0[lane + 32 * q];
    #pragma unroll
    for (int q = 0; q < 4; q++) b0[q] = rb0[lane + 32 * q];
    #pragma unroll
    for (int q = 0; q < 4; q++) a1[q] = ra1[lane + 32 * q];
    #pragma unroll
    for (int q = 0; q < 4; q++) b1[q] = rb1[lane + 32 * q];

    emit_pair(r0, lane, a0, b0);
    emit_pair(r1, lane, a1, b1);
}

// ============================================================
// Kernel 2: symmetric e4m3 GEMM (EXACT R8 form — best measured).
// 128x128 tiles, 256 threads = 4(m) x 2(n) warps of 32x64.
// ============================================================
__global__ void __launch_bounds__(256, 2) gemm_expsum_k()
{
    const int brow = blockIdx.y;
    const int bcol = blockIdx.x;
    if (brow > bcol) return;

    extern __shared__ __align__(128) char smem[];
    const uint32_t sbase = smem_u32(smem);

    const int tid  = threadIdx.x;
    const int lane = tid & 31;
    const int wid  = tid >> 5;
    const int warp_m = wid >> 1;
    const int warp_n = wid & 1;

    const uint8_t* Ab = g_z8 + (size_t)(brow * 128) * D;
    const uint8_t* Bb = g_z8 + (size_t)(bcol * 128) * D;

    auto load_chunk = [&](int c) {
        const uint32_t sa = sbase + (uint32_t)(c & 1) * BUF_BYTES;
        const uint32_t sb = sa + TILE_BYTES;
        const int k0 = c * 128;
        #pragma unroll
        for (int i = 0; i < 4; i++) {
            int idx = tid + i * 256;
            int row = idx >> 3, cc = idx & 7;
            uint32_t so = (uint32_t)(row * ROWB + cc * 16);
            const uint8_t* ga = Ab + (size_t)row * D + k0 + cc * 16;
            const uint8_t* gb = Bb + (size_t)row * D + k0 + cc * 16;
            asm volatile("cp.async.cg.shared.global [%0], [%1], 16;" :: "r"(sa + so), "l"(ga));
            asm volatile("cp.async.cg.shared.global [%0], [%1], 16;" :: "r"(sb + so), "l"(gb));
        }
        asm volatile("cp.async.commit_group;");
    };

    float acc[2][8][4];
    #pragma unroll
    for (int mf = 0; mf < 2; mf++)
        #pragma unroll
        for (int nf = 0; nf < 8; nf++)
            #pragma unroll
            for (int e = 0; e < 4; e++) acc[mf][nf][e] = 0.0f;

    load_chunk(0);

    #pragma unroll 1
    for (int c = 0; c < 4; c++) {
        if (c < 3) {
            load_chunk(c + 1);
            asm volatile("cp.async.wait_group 1;");
        } else {
            asm volatile("cp.async.wait_group 0;");
        }
        __syncthreads();

        const uint32_t sa = sbase + (uint32_t)(c & 1) * BUF_BYTES;
        const uint32_t sb = sa + TILE_BYTES;

        #pragma unroll
        for (int ks = 0; ks < 4; ks++) {
            uint32_t a[2][4];
            #pragma unroll
            for (int mf = 0; mf < 2; mf++) {
                int row = warp_m * 32 + mf * 16 + (lane & 15);
                int col = ks * 32 + (lane >> 4) * 16;
                uint32_t addr = sa + (uint32_t)(row * ROWB + col);
                asm volatile("ldmatrix.sync.aligned.m8n8.x4.shared.b16 {%0,%1,%2,%3},[%4];"
                    : "=r"(a[mf][0]), "=r"(a[mf][1]), "=r"(a[mf][2]), "=r"(a[mf][3])
                    : "r"(addr));
            }
            #pragma unroll
            for (int nf16 = 0; nf16 < 4; nf16++) {
                int sub = lane >> 3, wi = lane & 7;
                int nrow = warp_n * 64 + nf16 * 16 + ((sub & 2) ? 8 : 0) + wi;
                int kcol = ks * 32 + ((sub & 1) ? 16 : 0);
                uint32_t addr = sb + (uint32_t)(nrow * ROWB + kcol);
                uint32_t b0, b1, b2, b3;
                asm volatile("ldmatrix.sync.aligned.m8n8.x4.shared.b16 {%0,%1,%2,%3},[%4];"
                    : "=r"(b0), "=r"(b1), "=r"(b2), "=r"(b3) : "r"(addr));
                #pragma unroll
                for (int mf = 0; mf < 2; mf++) {
                    float* c0 = acc[mf][2 * nf16];
                    float* c1 = acc[mf][2 * nf16 + 1];
                    asm volatile(
                        "mma.sync.aligned.m16n8k32.row.col.f32.e4m3.e4m3.f32 "
                        "{%0,%1,%2,%3},{%4,%5,%6,%7},{%8,%9},{%0,%1,%2,%3};"
                        : "+f"(c0[0]), "+f"(c0[1]), "+f"(c0[2]), "+f"(c0[3])
                        : "r"(a[mf][0]), "r"(a[mf][1]), "r"(a[mf][2]), "r"(a[mf][3]),
                          "r"(b0), "r"(b1));
                    asm volatile(
                        "mma.sync.aligned.m16n8k32.row.col.f32.e4m3.e4m3.f32 "
                        "{%0,%1,%2,%3},{%4,%5,%6,%7},{%8,%9},{%0,%1,%2,%3};"
                        : "+f"(c1[0]), "+f"(c1[1]), "+f"(c1[2]), "+f"(c1[3])
                        : "r"(a[mf][0]), "r"(a[mf][1]), "r"(a[mf][2]), "r"(a[mf][3]),
                          "r"(b2), "r"(b3));
                }
            }
        }
        __syncthreads();
    }

    // --- epilogue: exp of 256x-scaled acc ---
    #pragma unroll
    for (int mf = 0; mf < 2; mf++)
        #pragma unroll
        for (int nf = 0; nf < 8; nf++)
            #pragma unroll
            for (int e = 0; e < 4; e++)
                acc[mf][nf][e] = expacc(acc[mf][nf][e]);

    #pragma unroll
    for (int mf = 0; mf < 2; mf++) {
        float rlo = 0.0f, rhi = 0.0f;
        #pragma unroll
        for (int nf = 0; nf < 8; nf++) {
            rlo += acc[mf][nf][0] + acc[mf][nf][1];
            rhi += acc[mf][nf][2] + acc[mf][nf][3];
        }
        rlo += __shfl_xor_sync(0xffffffffu, rlo, 1);
        rlo += __shfl_xor_sync(0xffffffffu, rlo, 2);
        rhi += __shfl_xor_sync(0xffffffffu, rhi, 1);
        rhi += __shfl_xor_sync(0xffffffffu, rhi, 2);
        if ((lane & 3) == 0) {
            int r0 = brow * 128 + warp_m * 32 + mf * 16 + (lane >> 2);
            int slot = bcol * 2 + warp_n;
            g_partial[(size_t)r0 * PSLOTS + slot] = rlo;
            g_partial[(size_t)(r0 + 8) * PSLOTS + slot] = rhi;
        }
    }

    if (brow != bcol) {
        float cs[16];
        #pragma unroll
        for (int nf = 0; nf < 8; nf++)
            #pragma unroll
            for (int e = 0; e < 2; e++)
                cs[nf * 2 + e] = acc[0][nf][e] + acc[0][nf][e + 2]
                               + acc[1][nf][e] + acc[1][nf][e + 2];
        #pragma unroll
        for (int i = 0; i < 16; i++) {
            cs[i] += __shfl_xor_sync(0xffffffffu, cs[i], 4);
            cs[i] += __shfl_xor_sync(0xffffffffu, cs[i], 8);
            cs[i] += __shfl_xor_sync(0xffffffffu, cs[i], 16);
        }
        float* scol = reinterpret_cast<float*>(smem);  // [4][128]
        __syncthreads();
        if (lane < 4) {
            #pragma unroll
            for (int nf = 0; nf < 8; nf++)
                #pragma unroll
                for (int e = 0; e < 2; e++) {
                    int col = warp_n * 64 + (nf >> 1) * 16 + (nf & 1) * 8 + lane * 2 + e;
                    scol[warp_m * 128 + col] = cs[nf * 2 + e];
                }
        }
        __syncthreads();
        if (tid < 128) {
            float v = scol[0 * 128 + tid] + scol[1 * 128 + tid];
            g_partial[(size_t)(bcol * 128 + tid) * PSLOTS + brow * 2 + 0] = v;
        } else {
            int ccol = tid - 128;
            float v = scol[2 * 128 + ccol] + scol[3 * 128 + ccol];
            g_partial[(size_t)(bcol * 128 + ccol) * PSLOTS + brow * 2 + 1] = v;
        }
    }
}

// ============================================================
// Kernel 3: single fused finalize (R8 form). Warp per row; last
// block reduces deterministically and self-resets g_cnt.
// ============================================================
__global__ void __launch_bounds__(1024) finalize_k(float* __restrict__ out)
{
    const int warp = threadIdx.x >> 5;
    const int lane = threadIdx.x & 31;
    const int row  = blockIdx.x * 32 + warp;

    float2 v2 = reinterpret_cast<const float2*>(g_partial + (size_t)row * PSLOTS)[lane];
    float s = v2.x + v2.y;
    #pragma unroll
    for (int o = 16; o > 0; o >>= 1)
        s += __shfl_down_sync(0xffffffffu, s, o);

    __shared__ float red[32];
    if (lane == 0) {
        float pos = g_pos[row], diag = g_diag[row];
        float tot = s - expdiag(diag) + exp2S(pos);
        red[warp] = logf(tot) - 2.0f * pos;
    }
    __syncthreads();

    __shared__ bool amlast;
    if (threadIdx.x < 32) {
        float v = red[threadIdx.x];
        #pragma unroll
        for (int o = 16; o > 0; o >>= 1)
            v += __shfl_down_sync(0xffffffffu, v, o);
        if (threadIdx.x == 0) {
            g_blk[blockIdx.x] = v;
            __threadfence();
            int old = atomicAdd(&g_cnt, 1);
            amlast = (old == FBLOCKS - 1);
        }
    }
    __syncthreads();

    if (amlast && threadIdx.x < 32) {
        __threadfence();
        float v = 0.0f;
        #pragma unroll
        for (int q = 0; q < FBLOCKS / 32; q++)
            v += g_blk[q * 32 + lane];
        #pragma unroll
        for (int o = 16; o > 0; o >>= 1)
            v += __shfl_down_sync(0xffffffffu, v, o);
        if (lane == 0) {
            out[0] = v / (float)NROWS;
            g_cnt = 0;
        }
    }
}

// ============================================================
extern "C" void kernel_launch(void* const* d_in, const int* in_sizes, int n_in,
                              void* d_out, int out_size)
{
    const float* zi = (const float*)d_in[0];
    const float* zj = (const float*)d_in[1];
    float* out = (float*)d_out;

    cudaFuncSetAttribute(gemm_expsum_k,
                         cudaFuncAttributeMaxDynamicSharedMemorySize, SMEM_TOT);

    normpos_k<<<256, 128>>>(zi, zj);
    dim3 grid(NROWS / 128, NROWS / 128);   // (32, 32), lower triangle exits
    gemm_expsum_k<<<grid, 256, SMEM_TOT>>>();
    finalize_k<<<FBLOCKS, 1024>>>(out);
}

// round 13
// speedup vs baseline: 1.1598x; 1.0047x over previous
#include <cuda_runtime.h>
#include <cuda_bf16.h>
#include <cuda_fp8.h>
#include <math.h>
#include <stdint.h>

// ---------------- problem constants ----------------
#define NROWS 4096      // 2*B
#define D     512
#define HALF  2048      // B
#define PSLOTS 64       // 32 column tiles * 2 halves
#define FBLOCKS 128     // finalize blocks
#define SCALE 16.0f     // fp8 pre-scale; S accumulator carries 256x

// ---------------- device scratch (no allocs) ----------------
__device__ uint8_t g_z8[NROWS * D];            // normalized rows, e4m3 x16 (2 MB)
__device__ float g_partial[NROWS * PSLOTS];    // exp row-sum partials (1 MB)
__device__ float g_pos[NROWS];
__device__ float g_diag[NROWS];
__device__ float g_blk[FBLOCKS];
__device__ int   g_cnt;                         // zero-init, self-resetting

// SMEM: two buffers, each A[128][144B] + B[128][144B]
#define ROWB 144
#define TILE_BYTES (128 * ROWB)          // 18432
#define BUF_BYTES  (2 * TILE_BYTES)      // 36864
#define SMEM_TOT   (2 * BUF_BYTES)       // 73728

// PDL primitives (sm_90 baseline PTX)
#define GRIDDEP_WAIT()    asm volatile("griddepcontrol.wait;" ::: "memory")
#define GRIDDEP_LAUNCH()  asm volatile("griddepcontrol.launch_dependents;" ::: "memory")

__device__ __forceinline__ uint32_t smem_u32(const void* p) {
    uint32_t a;
    asm("{ .reg .u64 t; cvta.to.shared.u64 t, %1; cvt.u32.u64 %0, t; }" : "=r"(a) : "l"(p));
    return a;
}

// exp(2S) from the 256x-scaled accumulator a=256*S: T4 with scale folded, squared.
__device__ __forceinline__ float expacc(float a) {
    float t = fmaf(a, 9.701278e-12f, 9.934107e-9f);
    t = fmaf(t, a, 7.62939453125e-6f);
    t = fmaf(t, a, 3.90625e-3f);
    t = fmaf(t, a, 1.0f);
    return t * t;
}
__device__ __forceinline__ float expdiag(float d) {
    float t = fmaf(d, 4.1666667e-2f, 1.6666667e-1f);
    t = fmaf(t, d, 0.5f);
    t = fmaf(t, d, 1.0f);
    t = fmaf(t, d, 1.0f);
    return t * t;
}
__device__ __forceinline__ float exp2S(float s) {
    float y = 0.5f * s;
    float p = fmaf(y, 8.3333333e-3f, 4.1666667e-2f);
    p = fmaf(p, y, 1.6666667e-1f);
    p = fmaf(p, y, 0.5f);
    p = fmaf(p, y, 1.0f);
    p = fmaf(p, y, 1.0f);
    p = p * p;
    return p * p;
}

__device__ __forceinline__ float warp_xor_sum(float v) {
    #pragma unroll
    for (int o = 16; o > 0; o >>= 1)
        v += __shfl_xor_sync(0xffffffffu, v, o);
    return v;
}

__device__ __forceinline__ uint16_t f2_to_e4m3x2(float2 f) {
    return (uint16_t)__nv_cvt_float2_to_fp8x2(f, __NV_SATFINITE, __NV_E4M3);
}
__device__ __forceinline__ float2 e4m3x2_to_f2(uint16_t u) {
    __half2_raw hr = __nv_cvt_fp8x2_to_halfraw2((__nv_fp8x2_storage_t)u, __NV_E4M3);
    __half2 h = *reinterpret_cast<__half2*>(&hr);
    return __half22float2(h);
}

// process one pair given its preloaded data; writes z8/pos/diag
__device__ __forceinline__ void emit_pair(int r, int lane,
                                          const float4* a, const float4* b)
{
    float sa = 0.0f, sb = 0.0f;
    #pragma unroll
    for (int q = 0; q < 4; q++) {
        sa += a[q].x * a[q].x + a[q].y * a[q].y + a[q].z * a[q].z + a[q].w * a[q].w;
        sb += b[q].x * b[q].x + b[q].y * b[q].y + b[q].z * b[q].z + b[q].w * b[q].w;
    }
    sa = warp_xor_sum(sa);
    sb = warp_xor_sum(sb);
    const float invA = 1.0f / fmaxf(sqrtf(sa), 1e-8f);
    const float invB = 1.0f / fmaxf(sqrtf(sb), 1e-8f);
    const float qA = invA * SCALE;
    const float qB = invB * SCALE;

    uint32_t* da = reinterpret_cast<uint32_t*>(g_z8 + (size_t)r * D);
    uint32_t* db = reinterpret_cast<uint32_t*>(g_z8 + (size_t)(r + HALF) * D);

    float pp = 0.0f, dA = 0.0f, dB = 0.0f;
    #pragma unroll
    for (int q = 0; q < 4; q++) {
        pp += (a[q].x * invA) * (b[q].x * invB) + (a[q].y * invA) * (b[q].y * invB)
            + (a[q].z * invA) * (b[q].z * invB) + (a[q].w * invA) * (b[q].w * invB);

        uint16_t a01 = f2_to_e4m3x2(make_float2(a[q].x * qA, a[q].y * qA));
        uint16_t a23 = f2_to_e4m3x2(make_float2(a[q].z * qA, a[q].w * qA));
        uint16_t b01 = f2_to_e4m3x2(make_float2(b[q].x * qB, b[q].y * qB));
        uint16_t b23 = f2_to_e4m3x2(make_float2(b[q].z * qB, b[q].w * qB));

        da[lane + 32 * q] = (uint32_t)a01 | ((uint32_t)a23 << 16);
        db[lane + 32 * q] = (uint32_t)b01 | ((uint32_t)b23 << 16);

        float2 fa0 = e4m3x2_to_f2(a01), fa1 = e4m3x2_to_f2(a23);
        float2 fb0 = e4m3x2_to_f2(b01), fb1 = e4m3x2_to_f2(b23);
        dA += fa0.x * fa0.x + fa0.y * fa0.y + fa1.x * fa1.x + fa1.y * fa1.y;
        dB += fb0.x * fb0.x + fb0.y * fb0.y + fb1.x * fb1.x + fb1.y * fb1.y;
    }
    pp = warp_xor_sum(pp);
    dA = warp_xor_sum(dA);
    dB = warp_xor_sum(dB);
    if (lane == 0) {
        g_pos[r] = pp; g_pos[r + HALF] = pp;
        g_diag[r] = dA * (1.0f / 256.0f);
        g_diag[r + HALF] = dB * (1.0f / 256.0f);
    }
}

// ============================================================
// Kernel 1: normalize + pos/diag (R12 form) + PDL trigger.
// ============================================================
__global__ void __launch_bounds__(128) normpos_k(const float* __restrict__ zi,
                                                 const float* __restrict__ zj)
{
    const int warp = threadIdx.x >> 5;
    const int lane = threadIdx.x & 31;
    const int w = blockIdx.x * 4 + warp;      // 0..1023
    const int r0 = w, r1 = w + 1024;

    const float4* ra0 = reinterpret_cast<const float4*>(zi + (size_t)r0 * D);
    const float4* rb0 = reinterpret_cast<const float4*>(zj + (size_t)r0 * D);
    const float4* ra1 = reinterpret_cast<const float4*>(zi + (size_t)r1 * D);
    const float4* rb1 = reinterpret_cast<const float4*>(zj + (size_t)r1 * D);

    float4 a0[4], b0[4], a1[4], b1[4];
    #pragma unroll
    for (int q = 0; q < 4; q++) a0[q] = ra0[lane + 32 * q];
    #pragma unroll
    for (int q = 0; q < 4; q++) b0[q] = rb0[lane + 32 * q];
    #pragma unroll
    for (int q = 0; q < 4; q++) a1[q] = ra1[lane + 32 * q];
    #pragma unroll
    for (int q = 0; q < 4; q++) b1[q] = rb1[lane + 32 * q];

    emit_pair(r0, lane, a0, b0);
    emit_pair(r1, lane, a1, b1);

    GRIDDEP_LAUNCH();   // all stores above are visible after dependent's wait
}

// ============================================================
// Kernel 2: symmetric e4m3 GEMM (R8/R12 form) + PDL wait/trigger.
// ============================================================
__global__ void __launch_bounds__(256, 2) gemm_expsum_k()
{
    const int brow = blockIdx.y;
    const int bcol = blockIdx.x;
    if (brow > bcol) return;

    GRIDDEP_WAIT();     // g_z8 / g_pos / g_diag ready

    extern __shared__ __align__(128) char smem[];
    const uint32_t sbase = smem_u32(smem);

    const int tid  = threadIdx.x;
    const int lane = tid & 31;
    const int wid  = tid >> 5;
    const int warp_m = wid >> 1;
    const int warp_n = wid & 1;

    const uint8_t* Ab = g_z8 + (size_t)(brow * 128) * D;
    const uint8_t* Bb = g_z8 + (size_t)(bcol * 128) * D;

    auto load_chunk = [&](int c) {
        const uint32_t sa = sbase + (uint32_t)(c & 1) * BUF_BYTES;
        const uint32_t sb = sa + TILE_BYTES;
        const int k0 = c * 128;
        #pragma unroll
        for (int i = 0; i < 4; i++) {
            int idx = tid + i * 256;
            int row = idx >> 3, cc = idx & 7;
            uint32_t so = (uint32_t)(row * ROWB + cc * 16);
            const uint8_t* ga = Ab + (size_t)row * D + k0 + cc * 16;
            const uint8_t* gb = Bb + (size_t)row * D + k0 + cc * 16;
            asm volatile("cp.async.cg.shared.global [%0], [%1], 16;" :: "r"(sa + so), "l"(ga));
            asm volatile("cp.async.cg.shared.global [%0], [%1], 16;" :: "r"(sb + so), "l"(gb));
        }
        asm volatile("cp.async.commit_group;");
    };

    float acc[2][8][4];
    #pragma unroll
    for (int mf = 0; mf < 2; mf++)
        #pragma unroll
        for (int nf = 0; nf < 8; nf++)
            #pragma unroll
            for (int e = 0; e < 4; e++) acc[mf][nf][e] = 0.0f;

    load_chunk(0);

    #pragma unroll 1
    for (int c = 0; c < 4; c++) {
        if (c < 3) {
            load_chunk(c + 1);
            asm volatile("cp.async.wait_group 1;");
        } else {
            asm volatile("cp.async.wait_group 0;");
        }
        __syncthreads();

        const uint32_t sa = sbase + (uint32_t)(c & 1) * BUF_BYTES;
        const uint32_t sb = sa + TILE_BYTES;

        #pragma unroll
        for (int ks = 0; ks < 4; ks++) {
            uint32_t a[2][4];
            #pragma unroll
            for (int mf = 0; mf < 2; mf++) {
                int row = warp_m * 32 + mf * 16 + (lane & 15);
                int col = ks * 32 + (lane >> 4) * 16;
                uint32_t addr = sa + (uint32_t)(row * ROWB + col);
                asm volatile("ldmatrix.sync.aligned.m8n8.x4.shared.b16 {%0,%1,%2,%3},[%4];"
                    : "=r"(a[mf][0]), "=r"(a[mf][1]), "=r"(a[mf][2]), "=r"(a[mf][3])
                    : "r"(addr));
            }
            #pragma unroll
            for (int nf16 = 0; nf16 < 4; nf16++) {
                int sub = lane >> 3, wi = lane & 7;
                int nrow = warp_n * 64 + nf16 * 16 + ((sub & 2) ? 8 : 0) + wi;
                int kcol = ks * 32 + ((sub & 1) ? 16 : 0);
                uint32_t addr = sb + (uint32_t)(nrow * ROWB + kcol);
                uint32_t b0, b1, b2, b3;
                asm volatile("ldmatrix.sync.aligned.m8n8.x4.shared.b16 {%0,%1,%2,%3},[%4];"
                    : "=r"(b0), "=r"(b1), "=r"(b2), "=r"(b3) : "r"(addr));
                #pragma unroll
                for (int mf = 0; mf < 2; mf++) {
                    float* c0 = acc[mf][2 * nf16];
                    float* c1 = acc[mf][2 * nf16 + 1];
                    asm volatile(
                        "mma.sync.aligned.m16n8k32.row.col.f32.e4m3.e4m3.f32 "
                        "{%0,%1,%2,%3},{%4,%5,%6,%7},{%8,%9},{%0,%1,%2,%3};"
                        : "+f"(c0[0]), "+f"(c0[1]), "+f"(c0[2]), "+f"(c0[3])
                        : "r"(a[mf][0]), "r"(a[mf][1]), "r"(a[mf][2]), "r"(a[mf][3]),
                          "r"(b0), "r"(b1));
                    asm volatile(
                        "mma.sync.aligned.m16n8k32.row.col.f32.e4m3.e4m3.f32 "
                        "{%0,%1,%2,%3},{%4,%5,%6,%7},{%8,%9},{%0,%1,%2,%3};"
                        : "+f"(c1[0]), "+f"(c1[1]), "+f"(c1[2]), "+f"(c1[3])
                        : "r"(a[mf][0]), "r"(a[mf][1]), "r"(a[mf][2]), "r"(a[mf][3]),
                          "r"(b2), "r"(b3));
                }
            }
        }
        __syncthreads();
    }

    // --- epilogue: exp of 256x-scaled acc ---
    #pragma unroll
    for (int mf = 0; mf < 2; mf++)
        #pragma unroll
        for (int nf = 0; nf < 8; nf++)
            #pragma unroll
            for (int e = 0; e < 4; e++)
                acc[mf][nf][e] = expacc(acc[mf][nf][e]);

    #pragma unroll
    for (int mf = 0; mf < 2; mf++) {
        float rlo = 0.0f, rhi = 0.0f;
        #pragma unroll
        for (int nf = 0; nf < 8; nf++) {
            rlo += acc[mf][nf][0] + acc[mf][nf][1];
            rhi += acc[mf][nf][2] + acc[mf][nf][3];
        }
        rlo += __shfl_xor_sync(0xffffffffu, rlo, 1);
        rlo += __shfl_xor_sync(0xffffffffu, rlo, 2);
        rhi += __shfl_xor_sync(0xffffffffu, rhi, 1);
        rhi += __shfl_xor_sync(0xffffffffu, rhi, 2);
        if ((lane & 3) == 0) {
            int r0 = brow * 128 + warp_m * 32 + mf * 16 + (lane >> 2);
            int slot = bcol * 2 + warp_n;
            g_partial[(size_t)r0 * PSLOTS + slot] = rlo;
            g_partial[(size_t)(r0 + 8) * PSLOTS + slot] = rhi;
        }
    }

    if (brow != bcol) {
        float cs[16];
        #pragma unroll
        for (int nf = 0; nf < 8; nf++)
            #pragma unroll
            for (int e = 0; e < 2; e++)
                cs[nf * 2 + e] = acc[0][nf][e] + acc[0][nf][e + 2]
                               + acc[1][nf][e] + acc[1][nf][e + 2];
        #pragma unroll
        for (int i = 0; i < 16; i++) {
            cs[i] += __shfl_xor_sync(0xffffffffu, cs[i], 4);
            cs[i] += __shfl_xor_sync(0xffffffffu, cs[i], 8);
            cs[i] += __shfl_xor_sync(0xffffffffu, cs[i], 16);
        }
        float* scol = reinterpret_cast<float*>(smem);  // [4][128]
        __syncthreads();
        if (lane < 4) {
            #pragma unroll
            for (int nf = 0; nf < 8; nf++)
                #pragma unroll
                for (int e = 0; e < 2; e++) {
                    int col = warp_n * 64 + (nf >> 1) * 16 + (nf & 1) * 8 + lane * 2 + e;
                    scol[warp_m * 128 + col] = cs[nf * 2 + e];
                }
        }
        __syncthreads();
        if (tid < 128) {
            float v = scol[0 * 128 + tid] + scol[1 * 128 + tid];
            g_partial[(size_t)(bcol * 128 + tid) * PSLOTS + brow * 2 + 0] = v;
        } else {
            int ccol = tid - 128;
            float v = scol[2 * 128 + ccol] + scol[3 * 128 + ccol];
            g_partial[(size_t)(bcol * 128 + ccol) * PSLOTS + brow * 2 + 1] = v;
        }
    }

    GRIDDEP_LAUNCH();   // partials visible to finalize after its wait
}

// ============================================================
// Kernel 3: single fused finalize (R12 form) + PDL wait.
// ============================================================
__global__ void __launch_bounds__(1024) finalize_k(float* __restrict__ out)
{
    GRIDDEP_WAIT();     // g_partial / g_pos / g_diag ready

    const int warp = threadIdx.x >> 5;
    const int lane = threadIdx.x & 31;
    const int row  = blockIdx.x * 32 + warp;

    float2 v2 = reinterpret_cast<const float2*>(g_partial + (size_t)row * PSLOTS)[lane];
    float s = v2.x + v2.y;
    #pragma unroll
    for (int o = 16; o > 0; o >>= 1)
        s += __shfl_down_sync(0xffffffffu, s, o);

    __shared__ float red[32];
    if (lane == 0) {
        float pos = g_pos[row], diag = g_diag[row];
        float tot = s - expdiag(diag) + exp2S(pos);
        red[warp] = logf(tot) - 2.0f * pos;
    }
    __syncthreads();

    __shared__ bool amlast;
    if (threadIdx.x < 32) {
        float v = red[threadIdx.x];
        #pragma unroll
        for (int o = 16; o > 0; o >>= 1)
            v += __shfl_down_sync(0xffffffffu, v, o);
        if (threadIdx.x == 0) {
            g_blk[blockIdx.x] = v;
            __threadfence();
            int old = atomicAdd(&g_cnt, 1);
            amlast = (old == FBLOCKS - 1);
        }
    }
    __syncthreads();

    if (amlast && threadIdx.x < 32) {
        __threadfence();
        float v = 0.0f;
        #pragma unroll
        for (int q = 0; q < FBLOCKS / 32; q++)
            v += g_blk[q * 32 + lane];
        #pragma unroll
        for (int o = 16; o > 0; o >>= 1)
            v += __shfl_down_sync(0xffffffffu, v, o);
        if (lane == 0) {
            out[0] = v / (float)NROWS;
            g_cnt = 0;
        }
    }
}

// ============================================================
extern "C" void kernel_launch(void* const* d_in, const int* in_sizes, int n_in,
                              void* d_out, int out_size)
{
    const float* zi = (const float*)d_in[0];
    const float* zj = (const float*)d_in[1];
    float* out = (float*)d_out;

    cudaFuncSetAttribute(gemm_expsum_k,
                         cudaFuncAttributeMaxDynamicSharedMemorySize, SMEM_TOT);

    normpos_k<<<256, 128>>>(zi, zj);

    // GEMM: PDL-dependent on normpos
    cudaLaunchAttribute attrs[1];
    attrs[0].id = cudaLaunchAttributeProgrammaticStreamSerialization;
    attrs[0].val.programmaticStreamSerializationAllowed = 1;

    cudaLaunchConfig_t cfg = {};
    cfg.gridDim = dim3(NROWS / 128, NROWS / 128);   // (32, 32)
    cfg.blockDim = dim3(256, 1, 1);
    cfg.dynamicSmemBytes = SMEM_TOT;
    cfg.stream = 0;
    cfg.attrs = attrs;
    cfg.numAttrs = 1;
    cudaLaunchKernelEx(&cfg, gemm_expsum_k);

    // finalize: PDL-dependent on GEMM
    cudaLaunchConfig_t cfg2 = {};
    cfg2.gridDim = dim3(FBLOCKS, 1, 1);
    cfg2.blockDim = dim3(1024, 1, 1);
    cfg2.dynamicSmemBytes = 0;
    cfg2.stream = 0;
    cfg2.attrs = attrs;
    cfg2.numAttrs = 1;
    cudaLaunchKernelEx(&cfg2, finalize_k, out);
}